// round 5
// baseline (speedup 1.0000x reference)
#include <cuda_runtime.h>
#include <math.h>

#define NT 2000
#define NPT 255
#define NC 16
#define NM 32
#define NG 16

typedef unsigned long long ull;

// padded layouts: g-stride 20 floats (80B) -> conflict-free broadcast loads,
// still 16B-aligned for float4.
#define GSTR 20
#define SLOT (NG*GSTR)                 // 320 floats per node slot / per B row
#define W_R0 0                         // 32 slots (written by levels 6,4,2)
#define W_R1 (32*SLOT)                 // 16 slots (written by levels 5,3,1)
#define W_FLOATS (48*SLOT)             // 61440 B
#define BF_FLOATS (NM*SLOT)            // 40960 B
#define DYN_FLOATS (W_FLOATS + BF_FLOATS + NM*NG*2)
#define DYN_BYTES  (DYN_FLOATS*4)      // 106496 B per CTA -> 2 CTAs/SM

__device__ float  g_smA[NC*NC*NG];     // softmaxed A, [p][c][g]
__device__ float  g_smBf[NM*NG*NC];    // softmaxed B, [m][g][c] (packed)
__device__ float  g_smPi[NC*NG];       // softmaxed Pi, [c][g]
__device__ float2 g_nu[NM*NG];         // leaf {1/nu, log2 nu} per (m,g)

// ---------------------------------------------------------------------------
// packed f32x2 + vector-LDS helpers
// ---------------------------------------------------------------------------
__device__ __forceinline__ ull pack2(float lo, float hi) {
    ull r; asm("mov.b64 %0, {%1, %2};" : "=l"(r) : "f"(lo), "f"(hi)); return r;
}
__device__ __forceinline__ void ffma2(ull& d, ull a, ull b) {
    asm("fma.rn.f32x2 %0, %1, %2, %0;" : "+l"(d) : "l"(a), "l"(b));
}
__device__ __forceinline__ void mul2(ull& d, ull a) {
    asm("mul.rn.f32x2 %0, %0, %1;" : "+l"(d) : "l"(a));
}
__device__ __forceinline__ float unpack_sum(ull v) {
    float lo, hi; asm("mov.b64 {%0, %1}, %2;" : "=f"(lo), "=f"(hi) : "l"(v));
    return lo + hi;
}
// one LDS.128 -> two FFMA2-ready 64-bit operands
__device__ __forceinline__ void lds2u64(ull& a, ull& b, const float* p) {
    unsigned addr = (unsigned)__cvta_generic_to_shared(p);
    asm("ld.shared.v2.u64 {%0, %1}, [%2];" : "=l"(a), "=l"(b) : "r"(addr));
}

// ---------------------------------------------------------------------------
// Prologue: softmaxes + [m][g][c] B + leaf-nu table. 1 block, 256 threads.
// ---------------------------------------------------------------------------
__global__ void htmm_softmax_kernel(const float* __restrict__ A,
                                    const float* __restrict__ B,
                                    const float* __restrict__ Pi) {
    int tid = threadIdx.x;
    int c = tid >> 4;
    int g = tid & 15;
    {   // A: softmax over p for each (c,g)
        float mx = -1e30f;
        #pragma unroll
        for (int p = 0; p < NC; p++) mx = fmaxf(mx, A[p*NC*NG + c*NG + g]);
        float e[NC]; float s = 0.f;
        #pragma unroll
        for (int p = 0; p < NC; p++) { e[p] = expf(A[p*NC*NG + c*NG + g] - mx); s += e[p]; }
        float rs = 1.f / s;
        #pragma unroll
        for (int p = 0; p < NC; p++) g_smA[p*NC*NG + c*NG + g] = e[p] * rs;
    }
    {   // B: softmax over m for each (c,g); store [m][g][c]
        float mx = -1e30f;
        #pragma unroll
        for (int m = 0; m < NM; m++) mx = fmaxf(mx, B[c*NM*NG + m*NG + g]);
        float s = 0.f;
        #pragma unroll
        for (int m = 0; m < NM; m++) s += expf(B[c*NM*NG + m*NG + g] - mx);
        float rs = 1.f / s;
        #pragma unroll
        for (int m = 0; m < NM; m++)
            g_smBf[m*NG*NC + g*NC + c] = expf(B[c*NM*NG + m*NG + g] - mx) * rs;
    }
    if (tid < NG) {   // Pi: softmax over c for each g
        int gg = tid;
        float mx = -1e30f;
        #pragma unroll
        for (int cc = 0; cc < NC; cc++) mx = fmaxf(mx, Pi[cc*NG + gg]);
        float s = 0.f;
        #pragma unroll
        for (int cc = 0; cc < NC; cc++) s += expf(Pi[cc*NG + gg] - mx);
        float rs = 1.f / s;
        #pragma unroll
        for (int cc = 0; cc < NC; cc++)
            g_smPi[cc*NG + gg] = expf(Pi[cc*NG + gg] - mx) * rs;
    }
    __syncthreads();
    // leaf nu: nu(m,g) = sum_c Pi[c,g]*smB[c,m,g]; store {1/nu, log2 nu}
    for (int i = tid; i < NM*NG; i += 256) {
        int m = i >> 4, gg = i & 15;
        float nu = 0.f;
        #pragma unroll
        for (int cc = 0; cc < NC; cc++)
            nu += g_smPi[cc*NG + gg] * g_smBf[m*NG*NC + gg*NC + cc];
        g_nu[i] = make_float2(1.f / nu, log2f(nu));
    }
}

// ---------------------------------------------------------------------------
// Main kernel: one CTA per tree, 2 CTAs/SM.
// Threads: pblk = tid&3 (states p = 4*pblk..+3), g = (tid>>2)&15, ng = tid>>6.
// Iterate over PARENTS: compute both sibling betas, store only their sum.
// All layouts use g-stride GSTR=20 (conflict-free across the warp's 8 g rows).
// ---------------------------------------------------------------------------
__global__ void __launch_bounds__(256, 2)
htmm_upward_kernel(const int* __restrict__ x, float* __restrict__ out) {
    extern __shared__ __align__(16) float sm[];
    float*  sW  = sm;                               // 48*SLOT floats
    float*  sBf = sm + W_FLOATS;                    // [m][g(pad)][c]
    float2* sNu = (float2*)(sm + W_FLOATS + BF_FLOATS);
    __shared__ int   sx[NPT];
    __shared__ float sacc[256];

    const int tid  = threadIdx.x;
    const int pblk = tid & 3;
    const int g    = (tid >> 2) & 15;
    const int ng   = tid >> 6;

    // ---- stage tables (A via sW scratch; consumed into regs before leaves) ----
    for (int i = tid; i < NC*NC*NG; i += 256) sW[i] = g_smA[i];
    for (int i = tid; i < NM*NG*NC; i += 256) {
        int m = i >> 8, r = i & 255;                 // r = g*16+c
        sBf[m*SLOT + (r >> 4)*GSTR + (r & 15)] = g_smBf[i];
    }
    for (int i = tid; i < NM*NG; i += 256) sNu[i] = g_nu[i];
    for (int i = tid; i < NPT; i += 256)   sx[i]  = x[blockIdx.x*NPT + i];
    __syncthreads();

    // A packed along c-pairs for this thread's states p = 4*pblk+ip
    ull A2[4][8];
    #pragma unroll
    for (int ip = 0; ip < 4; ip++) {
        int p = 4*pblk + ip;
        #pragma unroll
        for (int c2 = 0; c2 < 8; c2++)
            A2[ip][c2] = pack2(sW[p*256 + (2*c2)*16 + g],
                               sW[p*256 + (2*c2+1)*16 + g]);
    }
    ull Pi2[8];
    #pragma unroll
    for (int c2 = 0; c2 < 8; c2++)
        Pi2[c2] = pack2(g_smPi[(2*c2)*16 + g], g_smPi[(2*c2+1)*16 + g]);
    __syncthreads();   // sW scratch may now be overwritten

    float accll = 0.f;   // accumulated in log2 units

    // ---- Level 6 (leaves fused): parents k in [0,32) ----
    for (int k = ng; k < 32; k += 4) {
        float wo0 = 0.f, wo1 = 0.f, wo2 = 0.f, wo3 = 0.f;
        #pragma unroll
        for (int sel = 0; sel < 2; sel++) {
            const int j  = 2*k + sel;                  // level-6 node
            const int m0 = sx[127 + 2*j], m1 = sx[128 + 2*j];
            const float2 n0 = sNu[m0*NG + g], n1 = sNu[m1*NG + g];
            const ull r0 = pack2(n0.x, n0.x);
            const ull r1 = pack2(n1.x, n1.x);
            const float* b0p = sBf + m0*SLOT + g*GSTR;
            const float* b1p = sBf + m1*SLOT + g*GSTR;
            ull a0 = 0ull, a1 = 0ull, a2 = 0ull, a3 = 0ull;
            #pragma unroll
            for (int c4 = 0; c4 < 4; c4++) {           // stream B in 16B chunks
                ull b0a, b0b, b1a, b1b;
                lds2u64(b0a, b0b, b0p + 4*c4);
                lds2u64(b1a, b1b, b1p + 4*c4);
                ull w = b0a; mul2(w, r0); ffma2(w, b1a, r1); mul2(w, Pi2[2*c4]);
                ffma2(a0, A2[0][2*c4], w);
                ffma2(a1, A2[1][2*c4], w);
                ffma2(a2, A2[2][2*c4], w);
                ffma2(a3, A2[3][2*c4], w);
                ull v = b0b; mul2(v, r0); ffma2(v, b1b, r1); mul2(v, Pi2[2*c4+1]);
                ffma2(a0, A2[0][2*c4+1], v);
                ffma2(a1, A2[1][2*c4+1], v);
                ffma2(a2, A2[2][2*c4+1], v);
                ffma2(a3, A2[3][2*c4+1], v);
            }
            accll += 0.25f * (n0.y + n1.y);            // leaf lls (log2, from table)

            const int mu = sx[63 + j];
            const float4 e4 = *(const float4*)(sBf + mu*SLOT + g*GSTR + 4*pblk);
            float bv0 = e4.x * unpack_sum(a0);
            float bv1 = e4.y * unpack_sum(a1);
            float bv2 = e4.z * unpack_sum(a2);
            float bv3 = e4.w * unpack_sum(a3);
            float s = (bv0 + bv1) + (bv2 + bv3);
            s += __shfl_xor_sync(0xffffffffu, s, 1);
            s += __shfl_xor_sync(0xffffffffu, s, 2);
            float rs = __fdividef(1.f, s);
            wo0 += bv0*rs; wo1 += bv1*rs; wo2 += bv2*rs; wo3 += bv3*rs;
            accll += 0.25f * __log2f(s);
        }
        *(float4*)(sW + W_R0 + k*SLOT + g*GSTR + 4*pblk) =
            make_float4(wo0, wo1, wo2, wo3);
    }
    __syncthreads();

    // ---- Levels 5..1 ----
    #pragma unroll 1
    for (int l = 5; l >= 1; l--) {
        const int nPar   = 1 << (l - 1);
        const int rbase  = (l & 1) ? W_R0 : W_R1;   // written by level l+1
        const int wbase  = (l & 1) ? W_R1 : W_R0;
        const int lstart = (1 << l) - 1;
        for (int k = ng; k < nPar; k += 4) {
            float wo0 = 0.f, wo1 = 0.f, wo2 = 0.f, wo3 = 0.f;
            #pragma unroll
            for (int sel = 0; sel < 2; sel++) {
                const int j = 2*k + sel;
                const float* wp = sW + rbase + j*SLOT + g*GSTR;
                ull w0,w1,w2,w3,w4,w5,w6,w7;
                lds2u64(w0, w1, wp);
                lds2u64(w2, w3, wp + 4);
                lds2u64(w4, w5, wp + 8);
                lds2u64(w6, w7, wp + 12);
                ull a0 = 0ull, a1 = 0ull, a2 = 0ull, a3 = 0ull;
                ull wv[8] = {w0,w1,w2,w3,w4,w5,w6,w7};
                #pragma unroll
                for (int c2 = 0; c2 < 8; c2++) {
                    ffma2(a0, A2[0][c2], wv[c2]);
                    ffma2(a1, A2[1][c2], wv[c2]);
                    ffma2(a2, A2[2][c2], wv[c2]);
                    ffma2(a3, A2[3][c2], wv[c2]);
                }
                const int mu = sx[lstart + j];
                const float4 e4 = *(const float4*)(sBf + mu*SLOT + g*GSTR + 4*pblk);
                float bv0 = e4.x * unpack_sum(a0);
                float bv1 = e4.y * unpack_sum(a1);
                float bv2 = e4.z * unpack_sum(a2);
                float bv3 = e4.w * unpack_sum(a3);
                float s = (bv0 + bv1) + (bv2 + bv3);
                s += __shfl_xor_sync(0xffffffffu, s, 1);
                s += __shfl_xor_sync(0xffffffffu, s, 2);
                // true nu = s/2; /2 cancels in normalization, -1 (log2) folded at end
                float rs = __fdividef(1.f, s);
                wo0 += bv0*rs; wo1 += bv1*rs; wo2 += bv2*rs; wo3 += bv3*rs;
                accll += 0.25f * __log2f(s);
            }
            *(float4*)(sW + wbase + k*SLOT + g*GSTR + 4*pblk) =
                make_float4(wo0, wo1, wo2, wo3);
        }
        __syncthreads();
    }

    // ---- Root (level 0): group 0 only ----
    if (ng == 0) {
        const float* wp = sW + W_R1 + g*GSTR;       // level 1 wrote R1 slot 0
        ull w0,w1,w2,w3,w4,w5,w6,w7;
        lds2u64(w0, w1, wp);
        lds2u64(w2, w3, wp + 4);
        lds2u64(w4, w5, wp + 8);
        lds2u64(w6, w7, wp + 12);
        ull a0 = 0ull, a1 = 0ull, a2 = 0ull, a3 = 0ull;
        ull wv[8] = {w0,w1,w2,w3,w4,w5,w6,w7};
        #pragma unroll
        for (int c2 = 0; c2 < 8; c2++) {
            ffma2(a0, A2[0][c2], wv[c2]);
            ffma2(a1, A2[1][c2], wv[c2]);
            ffma2(a2, A2[2][c2], wv[c2]);
            ffma2(a3, A2[3][c2], wv[c2]);
        }
        const int mu = sx[0];
        const float4 e4 = *(const float4*)(sBf + mu*SLOT + g*GSTR + 4*pblk);
        float s = (e4.x*unpack_sum(a0) + e4.y*unpack_sum(a1))
                + (e4.z*unpack_sum(a2) + e4.w*unpack_sum(a3));
        s += __shfl_xor_sync(0xffffffffu, s, 1);
        s += __shfl_xor_sync(0xffffffffu, s, 2);
        accll += 0.25f * __log2f(s);
    }

    // ---- Deterministic per-g reduction over the 16 threads sharing g ----
    sacc[tid] = accll;
    __syncthreads();
    if (tid < NG) {
        float s = 0.f;
        #pragma unroll
        for (int kk = 0; kk < 16; kk++)
            s += sacc[(kk >> 2)*64 + tid*4 + (kk & 3)];
        // 127 internal nodes each owe -1 in log2 (folded BF=2 mean); convert to ln
        out[blockIdx.x*NG + tid] = 0.69314718055994530942f * (s - 127.0f);
    }
}

// ---------------------------------------------------------------------------
extern "C" void kernel_launch(void* const* d_in, const int* in_sizes, int n_in,
                              void* d_out, int out_size) {
    const float* A  = (const float*)d_in[0];
    const float* B  = (const float*)d_in[1];
    const float* Pi = (const float*)d_in[2];
    const int*   x  = (const int*)  d_in[3];
    float* out = (float*)d_out;

    cudaFuncSetAttribute(htmm_upward_kernel,
                         cudaFuncAttributeMaxDynamicSharedMemorySize, DYN_BYTES);

    htmm_softmax_kernel<<<1, 256>>>(A, B, Pi);
    htmm_upward_kernel<<<NT, 256, DYN_BYTES>>>(x, out);
}